// round 3
// baseline (speedup 1.0000x reference)
#include <cuda_runtime.h>
#include <cuda_bf16.h>

// Problem constants (fixed by reference setup_inputs)
#define BATCH 4096
#define CELL  400
#define KMIX  10      // K gaussian components
#define TLEN  256     // text_len
#define VDIM  80
#define RPB   16      // batch rows per block in kernel A
#define NTA   256
#define NTB   320

// phi scratch: [BATCH, TLEN] fp32 = 4 MB (device global, allocation-free)
__device__ float g_phi[(size_t)BATCH * TLEN];

// Dynamic shared layout for kernel A (floats):
//   sW    [3K*CELL] = 12000
//   sx    [RPB*CELL] = 6400
//   sp    [RPB*3K]  = 480
//   sal/sbe/ska [RPB*K] = 160 each
//   sbias [32]
#define SMEM_A_FLOATS (12000 + 6400 + 480 + 3*160 + 32)
#define SMEM_A_BYTES  (SMEM_A_FLOATS * 4)

__global__ __launch_bounds__(NTA)
void params_phi_kernel(const float* __restrict__ x,
                       const float* __restrict__ kappa_old,
                       const float* __restrict__ W,
                       const float* __restrict__ bias,
                       float* __restrict__ out_kappa)
{
    extern __shared__ float smem[];
    float* sW    = smem;                   // 12000
    float* sx    = sW + 12000;             // 6400
    float* sp    = sx + 6400;              // 480  [RPB][30]
    float* sal   = sp + 480;               // 160  [RPB][10]
    float* sbe   = sal + 160;
    float* ska   = sbe + 160;
    float* sbias = ska + 160;

    const int tid = threadIdx.x;
    const int b0  = blockIdx.x * RPB;

    // ---- stage W (float4) + bias + 16 x rows (float4) ----
    const float4* W4 = (const float4*)W;
    for (int i = tid; i < 12000 / 4; i += NTA) ((float4*)sW)[i] = W4[i];
    if (tid < 3 * KMIX) sbias[tid] = bias[tid];
    const float4* x4 = (const float4*)(x + (size_t)b0 * CELL);
    for (int i = tid; i < RPB * CELL / 4; i += NTA) ((float4*)sx)[i] = x4[i];
    __syncthreads();

    // ---- mat-vec: each warp computes 2 rows x 30 params ----
    const int warp = tid >> 5;
    const int lane = tid & 31;
    const int r0 = warp * 2, r1 = warp * 2 + 1;
    float acc0[3 * KMIX], acc1[3 * KMIX];
    #pragma unroll
    for (int p = 0; p < 3 * KMIX; p++) { acc0[p] = 0.0f; acc1[p] = 0.0f; }

    for (int c = lane; c < CELL; c += 32) {
        const float xv0 = sx[r0 * CELL + c];
        const float xv1 = sx[r1 * CELL + c];
        #pragma unroll
        for (int p = 0; p < 3 * KMIX; p++) {
            const float w = sW[p * CELL + c];
            acc0[p] += xv0 * w;
            acc1[p] += xv1 * w;
        }
    }
    #pragma unroll
    for (int p = 0; p < 3 * KMIX; p++) {
        float s0 = acc0[p], s1 = acc1[p];
        #pragma unroll
        for (int off = 16; off > 0; off >>= 1) {
            s0 += __shfl_xor_sync(0xffffffffu, s0, off);
            s1 += __shfl_xor_sync(0xffffffffu, s1, off);
        }
        if (lane == 0) {
            sp[r0 * 3 * KMIX + p] = s0 + sbias[p];
            sp[r1 * 3 * KMIX + p] = s1 + sbias[p];
        }
    }
    __syncthreads();

    // ---- alpha/beta/kappa transforms; write kappa out ----
    if (tid < RPB * KMIX) {
        const int r = tid / KMIX, k = tid % KMIX;
        const float* prow = sp + r * 3 * KMIX;
        const float kap = kappa_old[(size_t)(b0 + r) * KMIX + k] + expf(prow[2 * KMIX + k]);
        sal[r * KMIX + k] = expf(prow[k]);
        sbe[r * KMIX + k] = expf(prow[KMIX + k]);
        ska[r * KMIX + k] = kap;
        out_kappa[(size_t)(b0 + r) * KMIX + k] = kap;
    }
    __syncthreads();

    // ---- phi: 16 rows x 256 t; thread tid = t ----
    const float u = (float)tid;   // NTA == TLEN
    for (int r = 0; r < RPB; r++) {
        float s = 0.0f;
        #pragma unroll
        for (int k = 0; k < KMIX; k++) {
            const float d = ska[r * KMIX + k] - u;
            s += sal[r * KMIX + k] * expf(-sbe[r * KMIX + k] * d * d);
        }
        g_phi[(size_t)(b0 + r) * TLEN + tid] = s;
    }
}

// ---- Kernel B: pure streaming einsum, float4 ----
__global__ __launch_bounds__(NTB)
void stream_kernel(const float* __restrict__ onehots,
                   float* __restrict__ out_weight)
{
    const int b   = blockIdx.x;
    const int tid = threadIdx.x;

    __shared__ float  sphi[TLEN];
    __shared__ float4 wpart[16 * 20];   // [t0][c]

    if (tid < TLEN) sphi[tid] = g_phi[(size_t)b * TLEN + tid];
    __syncthreads();

    const float4* oh = (const float4*)(onehots + (size_t)b * TLEN * VDIM);
    const int c  = tid % 20;    // float4 column (v/4)
    const int t0 = tid / 20;    // 0..15

    float4 acc = make_float4(0.f, 0.f, 0.f, 0.f);
    #pragma unroll
    for (int j = 0; j < 16; j++) {
        const int t = t0 + j * 16;
        const float  p = sphi[t];
        const float4 o = oh[t * 20 + c];
        acc.x += p * o.x; acc.y += p * o.y; acc.z += p * o.z; acc.w += p * o.w;
    }
    wpart[t0 * 20 + c] = acc;
    __syncthreads();

    if (tid < VDIM) {
        const float* wp = (const float*)wpart;
        float s = 0.0f;
        #pragma unroll
        for (int j = 0; j < 16; j++) s += wp[j * VDIM + tid];
        out_weight[(size_t)b * VDIM + tid] = s;
    }
}

extern "C" void kernel_launch(void* const* d_in, const int* in_sizes, int n_in,
                              void* d_out, int out_size)
{
    const float* x         = (const float*)d_in[0];   // [B, CELL]
    const float* kappa_old = (const float*)d_in[1];   // [B, K]
    const float* onehots   = (const float*)d_in[2];   // [B, T, V]
    const float* W         = (const float*)d_in[3];   // [3K, CELL]
    const float* bias      = (const float*)d_in[4];   // [3K]

    float* out_weight = (float*)d_out;                        // [B, V]
    float* out_kappa  = (float*)d_out + (size_t)BATCH * VDIM; // [B, K]

    cudaFuncSetAttribute(params_phi_kernel,
                         cudaFuncAttributeMaxDynamicSharedMemorySize, SMEM_A_BYTES);

    params_phi_kernel<<<BATCH / RPB, NTA, SMEM_A_BYTES>>>(x, kappa_old, W, bias, out_kappa);
    stream_kernel<<<BATCH, NTB>>>(onehots, out_weight);
}

// round 4
// speedup vs baseline: 1.0233x; 1.0233x over previous
#include <cuda_runtime.h>
#include <cuda_bf16.h>

// Problem constants (fixed by reference setup_inputs)
#define BATCH 4096
#define CELL  400
#define KMIX  10      // K gaussian components
#define TLEN  256     // text_len
#define VDIM  80
#define RPB   16      // batch rows per block in kernel A
#define NTA   256
#define NTB   320

// phi scratch: [BATCH, TLEN] fp32 = 4 MB (device global, allocation-free)
__device__ float g_phi[(size_t)BATCH * TLEN];

// Dynamic shared layout for kernel A (floats):
//   sW    [3K*CELL] = 12000
//   sx    [RPB*CELL] = 6400
//   sp    [RPB*3K]  = 480
//   sal/sbe/ska [RPB*K] = 160 each
//   sbias [32]
#define SMEM_A_FLOATS (12000 + 6400 + 480 + 3*160 + 32)
#define SMEM_A_BYTES  (SMEM_A_FLOATS * 4)

__global__ __launch_bounds__(NTA)
void params_phi_kernel(const float* __restrict__ x,
                       const float* __restrict__ kappa_old,
                       const float* __restrict__ W,
                       const float* __restrict__ bias,
                       float* __restrict__ out_kappa)
{
    extern __shared__ float smem[];
    float* sW    = smem;                   // 12000
    float* sx    = sW + 12000;             // 6400
    float* sp    = sx + 6400;              // 480  [RPB][30]
    float* sal   = sp + 480;               // 160  [RPB][10]
    float* sbe   = sal + 160;
    float* ska   = sbe + 160;
    float* sbias = ska + 160;

    const int tid = threadIdx.x;
    const int b0  = blockIdx.x * RPB;

    // ---- stage W (float4) + bias + 16 x rows (float4) ----
    const float4* W4 = (const float4*)W;
    for (int i = tid; i < 12000 / 4; i += NTA) ((float4*)sW)[i] = W4[i];
    if (tid < 3 * KMIX) sbias[tid] = bias[tid];
    const float4* x4 = (const float4*)(x + (size_t)b0 * CELL);
    for (int i = tid; i < RPB * CELL / 4; i += NTA) ((float4*)sx)[i] = x4[i];
    __syncthreads();

    // ---- mat-vec: each warp computes 2 rows x 30 params ----
    const int warp = tid >> 5;
    const int lane = tid & 31;
    const int r0 = warp * 2, r1 = warp * 2 + 1;
    float acc0[3 * KMIX], acc1[3 * KMIX];
    #pragma unroll
    for (int p = 0; p < 3 * KMIX; p++) { acc0[p] = 0.0f; acc1[p] = 0.0f; }

    for (int c = lane; c < CELL; c += 32) {
        const float xv0 = sx[r0 * CELL + c];
        const float xv1 = sx[r1 * CELL + c];
        #pragma unroll
        for (int p = 0; p < 3 * KMIX; p++) {
            const float w = sW[p * CELL + c];
            acc0[p] += xv0 * w;
            acc1[p] += xv1 * w;
        }
    }
    #pragma unroll
    for (int p = 0; p < 3 * KMIX; p++) {
        float s0 = acc0[p], s1 = acc1[p];
        #pragma unroll
        for (int off = 16; off > 0; off >>= 1) {
            s0 += __shfl_xor_sync(0xffffffffu, s0, off);
            s1 += __shfl_xor_sync(0xffffffffu, s1, off);
        }
        if (lane == 0) {
            sp[r0 * 3 * KMIX + p] = s0 + sbias[p];
            sp[r1 * 3 * KMIX + p] = s1 + sbias[p];
        }
    }
    __syncthreads();

    // ---- alpha/beta/kappa transforms; write kappa out ----
    // __expf: MUFU.EX2-based, rel err ~2^-21, well inside 1e-3 tolerance
    if (tid < RPB * KMIX) {
        const int r = tid / KMIX, k = tid % KMIX;
        const float* prow = sp + r * 3 * KMIX;
        const float kap = kappa_old[(size_t)(b0 + r) * KMIX + k] + __expf(prow[2 * KMIX + k]);
        sal[r * KMIX + k] = __expf(prow[k]);
        sbe[r * KMIX + k] = __expf(prow[KMIX + k]);
        ska[r * KMIX + k] = kap;
        out_kappa[(size_t)(b0 + r) * KMIX + k] = kap;
    }
    __syncthreads();

    // ---- phi: 16 rows x 256 t; thread tid = t ----
    const float u = (float)tid;   // NTA == TLEN
    #pragma unroll 4
    for (int r = 0; r < RPB; r++) {
        float s = 0.0f;
        #pragma unroll
        for (int k = 0; k < KMIX; k++) {
            const float d = ska[r * KMIX + k] - u;
            s += sal[r * KMIX + k] * __expf(-sbe[r * KMIX + k] * d * d);
        }
        g_phi[(size_t)(b0 + r) * TLEN + tid] = s;
    }
}

// ---- Kernel B: pure streaming einsum, float4 (UNCHANGED: 52.1us @ 83.6% DRAM) ----
__global__ __launch_bounds__(NTB)
void stream_kernel(const float* __restrict__ onehots,
                   float* __restrict__ out_weight)
{
    const int b   = blockIdx.x;
    const int tid = threadIdx.x;

    __shared__ float  sphi[TLEN];
    __shared__ float4 wpart[16 * 20];   // [t0][c]

    if (tid < TLEN) sphi[tid] = g_phi[(size_t)b * TLEN + tid];
    __syncthreads();

    const float4* oh = (const float4*)(onehots + (size_t)b * TLEN * VDIM);
    const int c  = tid % 20;    // float4 column (v/4)
    const int t0 = tid / 20;    // 0..15

    float4 acc = make_float4(0.f, 0.f, 0.f, 0.f);
    #pragma unroll
    for (int j = 0; j < 16; j++) {
        const int t = t0 + j * 16;
        const float  p = sphi[t];
        const float4 o = oh[t * 20 + c];
        acc.x += p * o.x; acc.y += p * o.y; acc.z += p * o.z; acc.w += p * o.w;
    }
    wpart[t0 * 20 + c] = acc;
    __syncthreads();

    if (tid < VDIM) {
        const float* wp = (const float*)wpart;
        float s = 0.0f;
        #pragma unroll
        for (int j = 0; j < 16; j++) s += wp[j * VDIM + tid];
        out_weight[(size_t)b * VDIM + tid] = s;
    }
}

extern "C" void kernel_launch(void* const* d_in, const int* in_sizes, int n_in,
                              void* d_out, int out_size)
{
    const float* x         = (const float*)d_in[0];   // [B, CELL]
    const float* kappa_old = (const float*)d_in[1];   // [B, K]
    const float* onehots   = (const float*)d_in[2];   // [B, T, V]
    const float* W         = (const float*)d_in[3];   // [3K, CELL]
    const float* bias      = (const float*)d_in[4];   // [3K]

    float* out_weight = (float*)d_out;                        // [B, V]
    float* out_kappa  = (float*)d_out + (size_t)BATCH * VDIM; // [B, K]

    cudaFuncSetAttribute(params_phi_kernel,
                         cudaFuncAttributeMaxDynamicSharedMemorySize, SMEM_A_BYTES);

    params_phi_kernel<<<BATCH / RPB, NTA, SMEM_A_BYTES>>>(x, kappa_old, W, bias, out_kappa);
    stream_kernel<<<BATCH, NTB>>>(onehots, out_weight);
}